// round 9
// baseline (speedup 1.0000x reference)
#include <cuda_runtime.h>

#define NN 8192
#define INDIM 512
#define HID 50
#define ZD 128
#define NCAT 64
#define EPSV 1e-8f
#define NWORK_MAX (NN/16 + NCAT)   // 16-row tiles
#define NFX (NN/32)                // fx blocks in prep
#define NFZ (NN/32)                // fz blocks in prep

typedef unsigned long long u64;

// ---------------- scratch ----------------------------------------------------
__device__ float g_fxs[NN*ZD];   // fx in sorted order
__device__ float g_fzs[NN*ZD];   // fz in sorted order
__device__ int   g_cnt[NCAT], g_start[NCAT];
__device__ int   g_sorted[NN];
__device__ int   g_pos[NN];
__device__ int   g_work[NWORK_MAX];
__device__ int   g_nwork;

// ---------------- f32x2 helpers ----------------------------------------------
__device__ __forceinline__ u64 dup2(float x){
    u64 r; asm("mov.b64 %0, {%1, %1};" : "=l"(r) : "f"(x)); return r;
}
__device__ __forceinline__ void fma2(u64 &d, u64 a, u64 b){
    asm("fma.rn.f32x2 %0, %1, %2, %0;" : "+l"(d) : "l"(a), "l"(b));
}
__device__ __forceinline__ float2 unpk(u64 v){
    float2 f; asm("mov.b64 {%0, %1}, %2;" : "=f"(f.x), "=f"(f.y) : "l"(v)); return f;
}
__device__ __forceinline__ float softplusf(float v){
    return fmaxf(v, 0.f) + log1pf(__expf(-fabsf(v)));
}

// ---------------- fused bucket sort (single block) ---------------------------
__global__ void bucket_kernel(const int* __restrict__ c){
    __shared__ int s_cnt[NCAT];
    __shared__ int s_cursor[NCAT];
    __shared__ int s_cat[NN];
    int tid = threadIdx.x;

    if (tid < NCAT) s_cnt[tid] = 0;
    __syncthreads();
    for (int i = tid; i < NN; i += 1024){
        int cc = c[i];
        cc = min(max(cc, 0), NCAT - 1);
        s_cat[i] = cc;
        atomicAdd(&s_cnt[cc], 1);
    }
    __syncthreads();
    if (tid == 0){
        int s = 0, w = 0;
        for (int cc = 0; cc < NCAT; cc++){
            s_cursor[cc] = s;
            g_start[cc]  = s;
            int n = s_cnt[cc];
            g_cnt[cc] = n;
            s += n;
            int nt = (n + 15) >> 4;                    // 16-row tiles
            for (int t = 0; t < nt; t++) g_work[w++] = (cc << 16) | t;
        }
        g_nwork = w;
    }
    __syncthreads();
    for (int i = tid; i < NN; i += 1024){
        int p = atomicAdd(&s_cursor[s_cat[i]], 1);
        g_sorted[p] = i;
        g_pos[i]    = p;
    }
}

// ---------------- prep: fx (blocks 0..NFX) + fz (blocks NFX..NFX+NFZ) -------
__global__ void prep_kernel(const float* __restrict__ x,  const float* __restrict__ W1,
                            const float* __restrict__ b1, const float* __restrict__ W2,
                            const float* __restrict__ b2, const float* __restrict__ z,
                            const float* __restrict__ Wz, const float* __restrict__ bz){
    __shared__ __align__(16) float sbuf[8064];
    __shared__ float aux128[128];
    __shared__ float aux64[64];
    __shared__ int   posS[32];
    int tid = threadIdx.x;

    if (blockIdx.x < NFX){
        // ================= fx = relu(x@W1+b1)@W2+b2, 32 rows =================
        float* As  = sbuf;            // [32][36]
        float* Bs  = sbuf + 1152;     // [32][64]
        float* Hs  = sbuf;            // [32][52]
        float* W2s = sbuf + 1664;     // [50][128]
        float* b1s = aux64;
        float* b2s = aux128;

        int row0 = blockIdx.x * 32;
        if (tid < 64)  b1s[tid] = (tid < HID) ? b1[tid] : 0.f;
        if (tid < 128) b2s[tid] = b2[tid];
        if (tid < 32)  posS[tid] = g_pos[row0 + tid];

        float4 w2r[7];
        #pragma unroll
        for (int i = 0; i < 7; i++){
            int q = tid + 256*i;
            if (q < 1600) w2r[i] = *(const float4*)&W2[q*4];
        }

        int ar = tid >> 3, ac4 = tid & 7;
        float4 pa = *(const float4*)&x[(size_t)(row0 + ar)*INDIM + ac4*4];
        float pb[8];
        #pragma unroll
        for (int i = 0; i < 8; i++){
            int e = tid + 256*i;
            int k = e >> 6, j = e & 63;
            pb[i] = (j < HID) ? W1[(size_t)k*HID + j] : 0.f;
        }

        int rg = (tid >> 4) * 2;
        int cg = (tid & 15) * 4;
        u64 acc2[2][2] = {};

        for (int t = 0; t < 16; t++){
            __syncthreads();
            *(float4*)&As[ar*36 + ac4*4] = pa;
            #pragma unroll
            for (int i = 0; i < 8; i++){
                int e = tid + 256*i;
                Bs[(e >> 6)*64 + (e & 63)] = pb[i];
            }
            __syncthreads();
            if (t < 15){
                int k0 = (t+1)*32;
                pa = *(const float4*)&x[(size_t)(row0 + ar)*INDIM + k0 + ac4*4];
                #pragma unroll
                for (int i = 0; i < 8; i++){
                    int e = tid + 256*i;
                    int k = e >> 6, j = e & 63;
                    pb[i] = (j < HID) ? W1[(size_t)(k0 + k)*HID + j] : 0.f;
                }
            }
            #pragma unroll
            for (int k = 0; k < 32; k++){
                u64 da0 = dup2(As[rg*36 + k]);
                u64 da1 = dup2(As[(rg+1)*36 + k]);
                ulonglong2 bb = *(const ulonglong2*)&Bs[k*64 + cg];
                fma2(acc2[0][0], da0, bb.x); fma2(acc2[0][1], da0, bb.y);
                fma2(acc2[1][0], da1, bb.x); fma2(acc2[1][1], da1, bb.y);
            }
        }
        __syncthreads();

        #pragma unroll
        for (int i = 0; i < 2; i++){
            float2 p0 = unpk(acc2[i][0]);
            float2 p1 = unpk(acc2[i][1]);
            float hv[4] = {p0.x, p0.y, p1.x, p1.y};
            #pragma unroll
            for (int j = 0; j < 4; j++){
                int cc = cg + j;
                if (cc < HID) Hs[(rg+i)*52 + cc] = fmaxf(hv[j] + b1s[cc], 0.f);
            }
        }
        #pragma unroll
        for (int i = 0; i < 7; i++){
            int q = tid + 256*i;
            if (q < 1600) *(float4*)&W2s[q*4] = w2r[i];
        }
        __syncthreads();

        {
            int r0 = (tid >> 5) * 4;
            int c0 = (tid & 31) * 4;
            u64 a2[4][2] = {};
            #pragma unroll
            for (int k = 0; k < HID; k++){
                ulonglong2 bb = *(const ulonglong2*)&W2s[k*128 + c0];
                #pragma unroll
                for (int i = 0; i < 4; i++){
                    u64 da = dup2(Hs[(r0+i)*52 + k]);
                    fma2(a2[i][0], da, bb.x);
                    fma2(a2[i][1], da, bb.y);
                }
            }
            #pragma unroll
            for (int i = 0; i < 4; i++){
                float2 p0 = unpk(a2[i][0]);
                float2 p1 = unpk(a2[i][1]);
                float4 v = make_float4(p0.x + b2s[c0], p0.y + b2s[c0+1],
                                       p1.x + b2s[c0+2], p1.y + b2s[c0+3]);
                *(float4*)&g_fxs[(size_t)posS[r0+i]*ZD + c0] = v;
            }
        }
    } else {
        // ================= fz = z@Wz+bz, 32 rows =============================
        float* Zs  = sbuf;            // [32][36]
        float* Wzt = sbuf + 1152;     // [32][132]
        float* bzs = aux128;

        int row0 = (blockIdx.x - NFX) * 32;
        if (tid < 128) bzs[tid] = bz[tid];
        if (tid < 32)  posS[tid] = g_pos[row0 + tid];

        int ar = tid >> 3, ac4 = tid & 7;
        float4 pz = *(const float4*)&z[(size_t)(row0 + ar)*ZD + ac4*4];
        float4 pw[4];
        #pragma unroll
        for (int i = 0; i < 4; i++){
            int q = tid + 256*i;
            pw[i] = *(const float4*)&Wz[(size_t)(q >> 5)*ZD + (q & 31)*4];
        }

        int rg = (tid >> 4) * 2;
        int cg = (tid & 15) * 4;
        u64 acc2[2][4] = {};

        for (int kt = 0; kt < 4; kt++){
            __syncthreads();
            *(float4*)&Zs[ar*36 + ac4*4] = pz;
            #pragma unroll
            for (int i = 0; i < 4; i++){
                int q = tid + 256*i;
                *(float4*)&Wzt[(q >> 5)*132 + (q & 31)*4] = pw[i];
            }
            __syncthreads();
            if (kt < 3){
                int k0 = (kt+1)*32;
                pz = *(const float4*)&z[(size_t)(row0 + ar)*ZD + k0 + ac4*4];
                #pragma unroll
                for (int i = 0; i < 4; i++){
                    int q = tid + 256*i;
                    pw[i] = *(const float4*)&Wz[(size_t)(k0 + (q >> 5))*ZD + (q & 31)*4];
                }
            }
            #pragma unroll
            for (int k = 0; k < 32; k++){
                u64 da0 = dup2(Zs[rg*36 + k]);
                u64 da1 = dup2(Zs[(rg+1)*36 + k]);
                ulonglong2 b0 = *(const ulonglong2*)&Wzt[k*132 + cg];
                ulonglong2 b1 = *(const ulonglong2*)&Wzt[k*132 + cg + 64];
                fma2(acc2[0][0], da0, b0.x); fma2(acc2[0][1], da0, b0.y);
                fma2(acc2[0][2], da0, b1.x); fma2(acc2[0][3], da0, b1.y);
                fma2(acc2[1][0], da1, b0.x); fma2(acc2[1][1], da1, b0.y);
                fma2(acc2[1][2], da1, b1.x); fma2(acc2[1][3], da1, b1.y);
            }
        }

        #pragma unroll
        for (int i = 0; i < 2; i++){
            size_t base = (size_t)posS[rg+i]*ZD;
            float2 p0 = unpk(acc2[i][0]), p1 = unpk(acc2[i][1]);
            float2 p2 = unpk(acc2[i][2]), p3 = unpk(acc2[i][3]);
            *(float4*)&g_fzs[base + cg] =
                make_float4(p0.x + bzs[cg],   p0.y + bzs[cg+1],
                            p1.x + bzs[cg+2], p1.y + bzs[cg+3]);
            *(float4*)&g_fzs[base + cg + 64] =
                make_float4(p2.x + bzs[cg+64], p2.y + bzs[cg+65],
                            p3.x + bzs[cg+66], p3.y + bzs[cg+67]);
        }
    }
}

// ---------------- fused u + neg + output, 16-row i-tiles ---------------------
// phase1: FxsT = sbuf[0..2560) pitch20 [k][r]; Wst = sbuf[2560..6784) pitch132
// phase2: Us   = sbuf[0..2112) pitch132;       Fs  = sbuf[2112..6336) pitch132
__global__ void uneg_kernel(const float* __restrict__ Ws, float* __restrict__ out){
    __shared__ __align__(16) float sbuf[6784];
    __shared__ float Ts[16];
    __shared__ int   gidx[16];
    float* FxsT = sbuf;
    float* Wst  = sbuf + 2560;
    float* Us   = sbuf;
    float* Fs   = sbuf + 2112;

    int w = blockIdx.x;
    if (w >= g_nwork) return;
    int item  = g_work[w];
    int cat   = item >> 16, tile = item & 0xffff;
    int start = g_start[cat], cnt = g_cnt[cat];
    int i0    = tile * 16;
    int ni    = min(16, cnt - i0);
    int tid   = threadIdx.x;

    if (tid < 16) gidx[tid] = (tid < ni) ? g_sorted[start + i0 + tid] : 0;

    // stage fx tile transposed: thread = (k8 = tid>>4, r = tid&15)
    {
        int r  = tid & 15;
        int k8 = tid >> 4;                     // cols k8*8 .. k8*8+7
        float4 v0 = make_float4(0.f,0.f,0.f,0.f), v1 = v0;
        if (r < ni){
            size_t base = (size_t)(start + i0 + r)*ZD + k8*8;
            v0 = *(const float4*)&g_fxs[base];
            v1 = *(const float4*)&g_fxs[base + 4];
        }
        int kb = k8*8;
        FxsT[(kb+0)*20 + r] = v0.x; FxsT[(kb+1)*20 + r] = v0.y;
        FxsT[(kb+2)*20 + r] = v0.z; FxsT[(kb+3)*20 + r] = v0.w;
        FxsT[(kb+4)*20 + r] = v1.x; FxsT[(kb+5)*20 + r] = v1.y;
        FxsT[(kb+6)*20 + r] = v1.z; FxsT[(kb+7)*20 + r] = v1.w;
    }

    const float* Wc = Ws + (size_t)cat*ZD*ZD;
    float4 pw[4];
    #pragma unroll
    for (int i = 0; i < 4; i++){
        int q = tid + 256*i;
        pw[i] = *(const float4*)&Wc[(size_t)(q >> 5)*ZD + (q & 31)*4];
    }
    float4 pf[4];
    {
        int nj0 = min(32, cnt);
        #pragma unroll
        for (int i = 0; i < 4; i++){
            int q = tid + 256*i;
            int r = q >> 5;
            pf[i] = make_float4(0.f,0.f,0.f,0.f);
            if (r < nj0) pf[i] = *(const float4*)&g_fzs[(size_t)(start + r)*ZD + (q & 31)*4];
        }
    }

    int r0 = (tid >> 5) * 2;     // warp-uniform: rows r0, r0+1 (0..14)
    int c0 = (tid & 31) * 4;
    u64 acc[4] = {};             // col j -> {row r0, row r0+1}

    for (int kt = 0; kt < ZD; kt += 32){
        __syncthreads();
        #pragma unroll
        for (int i = 0; i < 4; i++){
            int q = tid + 256*i;
            *(float4*)&Wst[(q >> 5)*132 + (q & 31)*4] = pw[i];
        }
        __syncthreads();
        if (kt < ZD - 32){
            #pragma unroll
            for (int i = 0; i < 4; i++){
                int q = tid + 256*i;
                pw[i] = *(const float4*)&Wc[(size_t)(kt + 32 + (q >> 5))*ZD + (q & 31)*4];
            }
        }
        #pragma unroll
        for (int k = 0; k < 32; k++){
            u64 av = *(const u64*)&FxsT[(kt+k)*20 + r0];      // rows r0,r0+1
            float4 bv = *(const float4*)&Wst[k*132 + c0];
            fma2(acc[0], av, dup2(bv.x));
            fma2(acc[1], av, dup2(bv.y));
            fma2(acc[2], av, dup2(bv.z));
            fma2(acc[3], av, dup2(bv.w));
        }
    }
    __syncthreads();             // phase-1 reads done

    {
        float2 q0 = unpk(acc[0]), q1 = unpk(acc[1]), q2 = unpk(acc[2]), q3 = unpk(acc[3]);
        *(float4*)&Us[ r0   *132 + c0] = make_float4(q0.x, q1.x, q2.x, q3.x);
        *(float4*)&Us[(r0+1)*132 + c0] = make_float4(q0.y, q1.y, q2.y, q3.y);
    }

    int jj = tid & 31;
    int ig = tid >> 5;           // warp owns rows ig*2, ig*2+1
    float sum[2] = {0.f, 0.f};

    for (int j0 = 0; j0 < cnt; j0 += 32){
        int nj = min(32, cnt - j0);
        __syncthreads();         // Us visible (1st) / Fs consumers done
        #pragma unroll
        for (int i = 0; i < 4; i++){
            int q = tid + 256*i;
            *(float4*)&Fs[(q >> 5)*132 + (q & 31)*4] = pf[i];
        }
        __syncthreads();
        if (j0 + 32 < cnt){
            int njn = min(32, cnt - j0 - 32);
            #pragma unroll
            for (int i = 0; i < 4; i++){
                int q = tid + 256*i;
                int r = q >> 5;
                pf[i] = make_float4(0.f,0.f,0.f,0.f);
                if (r < njn) pf[i] = *(const float4*)&g_fzs[(size_t)(start + j0 + 32 + r)*ZD + (q & 31)*4];
            }
        }

        u64 a2[2] = {};
        #pragma unroll
        for (int k0 = 0; k0 < ZD; k0 += 4){
            ulonglong2 f = *(const ulonglong2*)&Fs[jj*132 + k0];
            #pragma unroll
            for (int m = 0; m < 2; m++){
                ulonglong2 u = *(const ulonglong2*)&Us[(ig*2 + m)*132 + k0];
                fma2(a2[m], u.x, f.x);
                fma2(a2[m], u.y, f.y);
            }
        }
        #pragma unroll
        for (int m = 0; m < 2; m++){
            float2 s = unpk(a2[m]);
            float d = s.x + s.y;
            int rr = ig*2 + m;
            int gj = i0 + rr;                         // diagonal j (within category)
            if (rr < ni && j0 == (gj & ~31) && jj == (gj & 31)) Ts[rr] = softplusf(d);
            float v = (jj < nj) ? softplusf(d) : 0.f;
            v += __shfl_xor_sync(0xffffffffu, v, 16);
            v += __shfl_xor_sync(0xffffffffu, v, 8);
            v += __shfl_xor_sync(0xffffffffu, v, 4);
            v += __shfl_xor_sync(0xffffffffu, v, 2);
            v += __shfl_xor_sync(0xffffffffu, v, 1);
            sum[m] += v;
        }
    }
    __syncthreads();             // Ts visible

    if (jj == 0){
        float inv = 1.f / (float)cnt;
        #pragma unroll
        for (int m = 0; m < 2; m++){
            int rr = ig*2 + m;
            if (rr < ni)
                out[gidx[rr]] = logf(Ts[rr] + EPSV) - logf(sum[m]*inv + EPSV);
        }
    }
}

// ---------------- launch ----------------------------------------------------
extern "C" void kernel_launch(void* const* d_in, const int* in_sizes, int n_in,
                              void* d_out, int out_size){
    const float* x  = (const float*)d_in[0];
    const int*   c  = (const int*)  d_in[1];
    const float* z  = (const float*)d_in[2];
    const float* W1 = (const float*)d_in[3];
    const float* b1 = (const float*)d_in[4];
    const float* W2 = (const float*)d_in[5];
    const float* b2 = (const float*)d_in[6];
    const float* Wz = (const float*)d_in[7];
    const float* bz = (const float*)d_in[8];
    const float* Ws = (const float*)d_in[9];
    float* out = (float*)d_out;

    bucket_kernel <<<1, 1024>>>(c);
    prep_kernel   <<<NFX + NFZ, 256>>>(x, W1, b1, W2, b2, z, Wz, bz);
    uneg_kernel   <<<NWORK_MAX, 256>>>(Ws, out);
}

// round 10
// speedup vs baseline: 1.3370x; 1.3370x over previous
#include <cuda_runtime.h>

#define NN 8192
#define INDIM 512
#define HID 50
#define ZD 128
#define NCAT 64
#define EPSV 1e-8f
#define NWORK_MAX (NN/32 + NCAT)
#define NFX (NN/32)
#define NFZ (NN/32)

typedef unsigned long long u64;

// ---------------- scratch ----------------------------------------------------
__device__ float g_fx[NN*ZD];    // natural order
__device__ float g_fz[NN*ZD];    // natural order
__device__ int   g_cnt[NCAT], g_start[NCAT];
__device__ int   g_sorted[NN];   // sorted pos -> original idx
__device__ int   g_work[NWORK_MAX];
__device__ int   g_nwork;

// ---------------- f32x2 helpers ----------------------------------------------
__device__ __forceinline__ u64 dup2(float x){
    u64 r; asm("mov.b64 %0, {%1, %1};" : "=l"(r) : "f"(x)); return r;
}
__device__ __forceinline__ void fma2(u64 &d, u64 a, u64 b){
    asm("fma.rn.f32x2 %0, %1, %2, %0;" : "+l"(d) : "l"(a), "l"(b));
}
__device__ __forceinline__ float2 unpk(u64 v){
    float2 f; asm("mov.b64 {%0, %1}, %2;" : "=f"(f.x), "=f"(f.y) : "l"(v)); return f;
}
__device__ __forceinline__ float softplusf(float v){
    return fmaxf(v, 0.f) + log1pf(__expf(-fabsf(v)));
}

// ---------------- prep: block0 = bucket, blocks 1..512 = fx/fz GEMMs ---------
__global__ void prep_kernel(const float* __restrict__ x,  const float* __restrict__ W1,
                            const float* __restrict__ b1, const float* __restrict__ W2,
                            const float* __restrict__ b2, const float* __restrict__ z,
                            const float* __restrict__ Wz, const float* __restrict__ bz,
                            const int*   __restrict__ c){
    __shared__ __align__(16) float sbuf[8064];
    __shared__ float aux128[128];
    __shared__ float aux64[64];
    __shared__ int   s_cnt[NCAT];
    __shared__ int   s_cursor[NCAT];
    int tid  = threadIdx.x;
    int lane = tid & 31;

    if (blockIdx.x == 0){
        // ================= bucket sort (warp-aggregated atomics) =============
        if (tid < NCAT) s_cnt[tid] = 0;
        __syncthreads();
        for (int i = tid; i < NN; i += 256){
            int cc = min(max(c[i], 0), NCAT - 1);
            unsigned m = __match_any_sync(0xffffffffu, cc);
            if ((m & ((1u << lane) - 1)) == 0) atomicAdd(&s_cnt[cc], __popc(m));
        }
        __syncthreads();
        if (tid == 0){
            int s = 0, w = 0;
            for (int cc = 0; cc < NCAT; cc++){
                s_cursor[cc] = s;
                g_start[cc]  = s;
                int n = s_cnt[cc];
                g_cnt[cc] = n;
                s += n;
                int nt = (n + 31) >> 5;
                for (int t = 0; t < nt; t++) g_work[w++] = (cc << 16) | t;
            }
            g_nwork = w;
        }
        __syncthreads();
        for (int i = tid; i < NN; i += 256){
            int cc = min(max(c[i], 0), NCAT - 1);
            unsigned m = __match_any_sync(0xffffffffu, cc);
            int leader = __ffs(m) - 1;
            int rank   = __popc(m & ((1u << lane) - 1));
            int base   = 0;
            if (lane == leader) base = atomicAdd(&s_cursor[cc], __popc(m));
            base = __shfl_sync(0xffffffffu, base, leader);
            g_sorted[base + rank] = i;
        }
    } else if (blockIdx.x <= NFX){
        // ================= fx = relu(x@W1+b1)@W2+b2, 32 rows =================
        float* As  = sbuf;            // [32][36]
        float* Bs  = sbuf + 1152;     // [32][64]
        float* Hs  = sbuf;            // [32][52]
        float* W2s = sbuf + 1664;     // [50][128]
        float* b1s = aux64;
        float* b2s = aux128;

        int row0 = (blockIdx.x - 1) * 32;
        if (tid < 64)  b1s[tid] = (tid < HID) ? b1[tid] : 0.f;
        if (tid < 128) b2s[tid] = b2[tid];

        float4 w2r[7];
        #pragma unroll
        for (int i = 0; i < 7; i++){
            int q = tid + 256*i;
            if (q < 1600) w2r[i] = *(const float4*)&W2[q*4];
        }

        int ar = tid >> 3, ac4 = tid & 7;
        float4 pa = *(const float4*)&x[(size_t)(row0 + ar)*INDIM + ac4*4];
        float pb[8];
        #pragma unroll
        for (int i = 0; i < 8; i++){
            int e = tid + 256*i;
            int k = e >> 6, j = e & 63;
            pb[i] = (j < HID) ? W1[(size_t)k*HID + j] : 0.f;
        }

        int rg = (tid >> 4) * 2;
        int cg = (tid & 15) * 4;
        u64 acc2[2][2] = {};

        for (int t = 0; t < 16; t++){
            __syncthreads();
            *(float4*)&As[ar*36 + ac4*4] = pa;
            #pragma unroll
            for (int i = 0; i < 8; i++){
                int e = tid + 256*i;
                Bs[(e >> 6)*64 + (e & 63)] = pb[i];
            }
            __syncthreads();
            if (t < 15){
                int k0 = (t+1)*32;
                pa = *(const float4*)&x[(size_t)(row0 + ar)*INDIM + k0 + ac4*4];
                #pragma unroll
                for (int i = 0; i < 8; i++){
                    int e = tid + 256*i;
                    int k = e >> 6, j = e & 63;
                    pb[i] = (j < HID) ? W1[(size_t)(k0 + k)*HID + j] : 0.f;
                }
            }
            #pragma unroll
            for (int k = 0; k < 32; k++){
                u64 da0 = dup2(As[rg*36 + k]);
                u64 da1 = dup2(As[(rg+1)*36 + k]);
                ulonglong2 bb = *(const ulonglong2*)&Bs[k*64 + cg];
                fma2(acc2[0][0], da0, bb.x); fma2(acc2[0][1], da0, bb.y);
                fma2(acc2[1][0], da1, bb.x); fma2(acc2[1][1], da1, bb.y);
            }
        }
        __syncthreads();

        #pragma unroll
        for (int i = 0; i < 2; i++){
            float2 p0 = unpk(acc2[i][0]);
            float2 p1 = unpk(acc2[i][1]);
            float hv[4] = {p0.x, p0.y, p1.x, p1.y};
            #pragma unroll
            for (int j = 0; j < 4; j++){
                int cc = cg + j;
                if (cc < HID) Hs[(rg+i)*52 + cc] = fmaxf(hv[j] + b1s[cc], 0.f);
            }
        }
        #pragma unroll
        for (int i = 0; i < 7; i++){
            int q = tid + 256*i;
            if (q < 1600) *(float4*)&W2s[q*4] = w2r[i];
        }
        __syncthreads();

        {
            int r0 = (tid >> 5) * 4;
            int c0 = (tid & 31) * 4;
            u64 a2[4][2] = {};
            #pragma unroll
            for (int k = 0; k < HID; k++){
                ulonglong2 bb = *(const ulonglong2*)&W2s[k*128 + c0];
                #pragma unroll
                for (int i = 0; i < 4; i++){
                    u64 da = dup2(Hs[(r0+i)*52 + k]);
                    fma2(a2[i][0], da, bb.x);
                    fma2(a2[i][1], da, bb.y);
                }
            }
            #pragma unroll
            for (int i = 0; i < 4; i++){
                float2 p0 = unpk(a2[i][0]);
                float2 p1 = unpk(a2[i][1]);
                float4 v = make_float4(p0.x + b2s[c0], p0.y + b2s[c0+1],
                                       p1.x + b2s[c0+2], p1.y + b2s[c0+3]);
                *(float4*)&g_fx[(size_t)(row0 + r0 + i)*ZD + c0] = v;
            }
        }
    } else {
        // ================= fz = z@Wz+bz, 32 rows =============================
        float* Zs  = sbuf;            // [32][36]
        float* Wzt = sbuf + 1152;     // [32][132]
        float* bzs = aux128;

        int row0 = (blockIdx.x - 1 - NFX) * 32;
        if (tid < 128) bzs[tid] = bz[tid];

        int ar = tid >> 3, ac4 = tid & 7;
        float4 pz = *(const float4*)&z[(size_t)(row0 + ar)*ZD + ac4*4];
        float4 pw[4];
        #pragma unroll
        for (int i = 0; i < 4; i++){
            int q = tid + 256*i;
            pw[i] = *(const float4*)&Wz[(size_t)(q >> 5)*ZD + (q & 31)*4];
        }

        int rg = (tid >> 4) * 2;
        int cg = (tid & 15) * 4;
        u64 acc2[2][4] = {};

        for (int kt = 0; kt < 4; kt++){
            __syncthreads();
            *(float4*)&Zs[ar*36 + ac4*4] = pz;
            #pragma unroll
            for (int i = 0; i < 4; i++){
                int q = tid + 256*i;
                *(float4*)&Wzt[(q >> 5)*132 + (q & 31)*4] = pw[i];
            }
            __syncthreads();
            if (kt < 3){
                int k0 = (kt+1)*32;
                pz = *(const float4*)&z[(size_t)(row0 + ar)*ZD + k0 + ac4*4];
                #pragma unroll
                for (int i = 0; i < 4; i++){
                    int q = tid + 256*i;
                    pw[i] = *(const float4*)&Wz[(size_t)(k0 + (q >> 5))*ZD + (q & 31)*4];
                }
            }
            #pragma unroll
            for (int k = 0; k < 32; k++){
                u64 da0 = dup2(Zs[rg*36 + k]);
                u64 da1 = dup2(Zs[(rg+1)*36 + k]);
                ulonglong2 b0 = *(const ulonglong2*)&Wzt[k*132 + cg];
                ulonglong2 b1 = *(const ulonglong2*)&Wzt[k*132 + cg + 64];
                fma2(acc2[0][0], da0, b0.x); fma2(acc2[0][1], da0, b0.y);
                fma2(acc2[0][2], da0, b1.x); fma2(acc2[0][3], da0, b1.y);
                fma2(acc2[1][0], da1, b0.x); fma2(acc2[1][1], da1, b0.y);
                fma2(acc2[1][2], da1, b1.x); fma2(acc2[1][3], da1, b1.y);
            }
        }

        #pragma unroll
        for (int i = 0; i < 2; i++){
            size_t base = (size_t)(row0 + rg + i)*ZD;
            float2 p0 = unpk(acc2[i][0]), p1 = unpk(acc2[i][1]);
            float2 p2 = unpk(acc2[i][2]), p3 = unpk(acc2[i][3]);
            *(float4*)&g_fz[base + cg] =
                make_float4(p0.x + bzs[cg],   p0.y + bzs[cg+1],
                            p1.x + bzs[cg+2], p1.y + bzs[cg+3]);
            *(float4*)&g_fz[base + cg + 64] =
                make_float4(p2.x + bzs[cg+64], p2.y + bzs[cg+65],
                            p3.x + bzs[cg+66], p3.y + bzs[cg+67]);
        }
    }
}

// ---------------- fused u + neg + output, 32-row i-tiles (gathered) ----------
// phase1: FxsT = sbuf[0..4608) pitch36 [k][r]; Wst = sbuf[4608..8832) pitch132
// phase2: Us = sbuf[0..4224) pitch132;  Fs = sbuf[4224..8448) pitch132
__global__ void uneg_kernel(const float* __restrict__ Ws, float* __restrict__ out){
    __shared__ __align__(16) float sbuf[8832];
    __shared__ float Ts[32];
    __shared__ int   gidx[32];
    float* FxsT = sbuf;
    float* Wst  = sbuf + 4608;
    float* Us   = sbuf;
    float* Fs   = sbuf + 4224;

    int w = blockIdx.x;
    if (w >= g_nwork) return;
    int item  = g_work[w];
    int cat   = item >> 16, tile = item & 0xffff;
    int start = g_start[cat], cnt = g_cnt[cat];
    int i0    = tile * 32;
    int ni    = min(32, cnt - i0);
    int tid   = threadIdx.x;

    if (tid < 32) gidx[tid] = (tid < ni) ? g_sorted[start + i0 + tid] : 0;

    // stage fx tile transposed (gather rows via g_sorted)
    {
        int r = tid & 31;
        int gi = 0; bool act = (r < ni);
        if (act) gi = g_sorted[start + i0 + r];
        #pragma unroll
        for (int i = 0; i < 4; i++){
            int k4 = (tid >> 5) + 8*i;
            float4 v = make_float4(0.f,0.f,0.f,0.f);
            if (act) v = *(const float4*)&g_fx[(size_t)gi*ZD + k4*4];
            FxsT[(k4*4+0)*36 + r] = v.x;
            FxsT[(k4*4+1)*36 + r] = v.y;
            FxsT[(k4*4+2)*36 + r] = v.z;
            FxsT[(k4*4+3)*36 + r] = v.w;
        }
    }

    const float* Wc = Ws + (size_t)cat*ZD*ZD;
    float4 pw[4];
    #pragma unroll
    for (int i = 0; i < 4; i++){
        int q = tid + 256*i;
        pw[i] = *(const float4*)&Wc[(size_t)(q >> 5)*ZD + (q & 31)*4];
    }
    // prefetch first Fs tile (gathered)
    float4 pf[4];
    {
        int nj0 = min(32, cnt);
        #pragma unroll
        for (int i = 0; i < 4; i++){
            int q = tid + 256*i;
            int r = q >> 5;
            pf[i] = make_float4(0.f,0.f,0.f,0.f);
            if (r < nj0){
                int gj = g_sorted[start + r];
                pf[i] = *(const float4*)&g_fz[(size_t)gj*ZD + (q & 31)*4];
            }
        }
    }

    int r0 = (tid >> 5) * 4;     // warp-uniform row group
    int c0 = (tid & 31) * 4;
    u64 acc2[4][2] = {};

    for (int kt = 0; kt < ZD; kt += 32){
        __syncthreads();
        #pragma unroll
        for (int i = 0; i < 4; i++){
            int q = tid + 256*i;
            *(float4*)&Wst[(q >> 5)*132 + (q & 31)*4] = pw[i];
        }
        __syncthreads();
        if (kt < ZD - 32){
            #pragma unroll
            for (int i = 0; i < 4; i++){
                int q = tid + 256*i;
                pw[i] = *(const float4*)&Wc[(size_t)(kt + 32 + (q >> 5))*ZD + (q & 31)*4];
            }
        }
        #pragma unroll
        for (int k = 0; k < 32; k++){
            ulonglong2 av = *(const ulonglong2*)&FxsT[(kt+k)*36 + r0];
            float4 bv = *(const float4*)&Wst[k*132 + c0];
            u64 d0 = dup2(bv.x), d1 = dup2(bv.y), d2 = dup2(bv.z), d3 = dup2(bv.w);
            fma2(acc2[0][0], av.x, d0); fma2(acc2[0][1], av.y, d0);
            fma2(acc2[1][0], av.x, d1); fma2(acc2[1][1], av.y, d1);
            fma2(acc2[2][0], av.x, d2); fma2(acc2[2][1], av.y, d2);
            fma2(acc2[3][0], av.x, d3); fma2(acc2[3][1], av.y, d3);
        }
    }
    __syncthreads();

    {
        float2 q00 = unpk(acc2[0][0]), q10 = unpk(acc2[1][0]),
               q20 = unpk(acc2[2][0]), q30 = unpk(acc2[3][0]);
        float2 q01 = unpk(acc2[0][1]), q11 = unpk(acc2[1][1]),
               q21 = unpk(acc2[2][1]), q31 = unpk(acc2[3][1]);
        *(float4*)&Us[(r0+0)*132 + c0] = make_float4(q00.x, q10.x, q20.x, q30.x);
        *(float4*)&Us[(r0+1)*132 + c0] = make_float4(q00.y, q10.y, q20.y, q30.y);
        *(float4*)&Us[(r0+2)*132 + c0] = make_float4(q01.x, q11.x, q21.x, q31.x);
        *(float4*)&Us[(r0+3)*132 + c0] = make_float4(q01.y, q11.y, q21.y, q31.y);
    }

    int jj = tid & 31;
    int ig = tid >> 5;
    float sum[4] = {0.f, 0.f, 0.f, 0.f};

    for (int j0 = 0; j0 < cnt; j0 += 32){
        int nj = min(32, cnt - j0);
        __syncthreads();
        #pragma unroll
        for (int i = 0; i < 4; i++){
            int q = tid + 256*i;
            *(float4*)&Fs[(q >> 5)*132 + (q & 31)*4] = pf[i];
        }
        __syncthreads();
        if (j0 + 32 < cnt){
            int njn = min(32, cnt - j0 - 32);
            #pragma unroll
            for (int i = 0; i < 4; i++){
                int q = tid + 256*i;
                int r = q >> 5;
                pf[i] = make_float4(0.f,0.f,0.f,0.f);
                if (r < njn){
                    int gj = g_sorted[start + j0 + 32 + r];
                    pf[i] = *(const float4*)&g_fz[(size_t)gj*ZD + (q & 31)*4];
                }
            }
        }

        u64 a4[4] = {};
        #pragma unroll
        for (int k0 = 0; k0 < ZD; k0 += 4){
            ulonglong2 f = *(const ulonglong2*)&Fs[jj*132 + k0];
            #pragma unroll
            for (int m = 0; m < 4; m++){
                ulonglong2 u = *(const ulonglong2*)&Us[(ig*4 + m)*132 + k0];
                fma2(a4[m], u.x, f.x);
                fma2(a4[m], u.y, f.y);
            }
        }
        #pragma unroll
        for (int m = 0; m < 4; m++){
            float2 s = unpk(a4[m]);
            float d = s.x + s.y;
            int rr = ig*4 + m;
            if (j0 == i0 && jj == rr && rr < ni) Ts[rr] = softplusf(d);  // diagonal = T
            float v = (jj < nj) ? softplusf(d) : 0.f;
            v += __shfl_xor_sync(0xffffffffu, v, 16);
            v += __shfl_xor_sync(0xffffffffu, v, 8);
            v += __shfl_xor_sync(0xffffffffu, v, 4);
            v += __shfl_xor_sync(0xffffffffu, v, 2);
            v += __shfl_xor_sync(0xffffffffu, v, 1);
            sum[m] += v;
        }
    }
    __syncthreads();

    if (jj == 0){
        float inv = 1.f / (float)cnt;
        #pragma unroll
        for (int m = 0; m < 4; m++){
            int rr = ig*4 + m;
            if (rr < ni)
                out[gidx[rr]] = logf(Ts[rr] + EPSV) - logf(sum[m]*inv + EPSV);
        }
    }
}

// ---------------- launch ----------------------------------------------------
extern "C" void kernel_launch(void* const* d_in, const int* in_sizes, int n_in,
                              void* d_out, int out_size){
    const float* x  = (const float*)d_in[0];
    const int*   c  = (const int*)  d_in[1];
    const float* z  = (const float*)d_in[2];
    const float* W1 = (const float*)d_in[3];
    const float* b1 = (const float*)d_in[4];
    const float* W2 = (const float*)d_in[5];
    const float* b2 = (const float*)d_in[6];
    const float* Wz = (const float*)d_in[7];
    const float* bz = (const float*)d_in[8];
    const float* Ws = (const float*)d_in[9];
    float* out = (float*)d_out;

    prep_kernel <<<1 + NFX + NFZ, 256>>>(x, W1, b1, W2, b2, z, Wz, bz, c);
    uneg_kernel <<<NWORK_MAX, 256>>>(Ws, out);
}